// round 7
// baseline (speedup 1.0000x reference)
#include <cuda_runtime.h>
#include <cuda_bf16.h>
#include <cuda_fp16.h>
#include <math.h>
#include <stdint.h>

// Problem constants
#define B_ 2
#define N_ 12288
#define D_ 256
#define CONF_THRESH 0.8f
#define JSPLIT 3
#define MARGIN 0.008f

// ---------------- device scratch (no allocations allowed) ----------------
__device__ __nv_bfloat16 g_Vhi[(size_t)B_ * N_ * D_];
__device__ __nv_bfloat16 g_Rhi[(size_t)B_ * N_ * D_];
__device__ float    g_Vf[(size_t)B_ * N_ * D_];
__device__ float    g_Rf[(size_t)B_ * N_ * D_];
__device__ __half   g_sims[(size_t)B_ * N_ * N_];   // approx sims, fp16
__device__ int      g_nval[B_];
__device__ int      g_ninv[B_];
__device__ int      g_nconf[B_];
__device__ unsigned g_rmax[B_ * N_];     // monotonic-encoded approx row max
__device__ double   g_contrib[B_];
__device__ int      g_mask_mode;         // 0=int32, 1=uint8, 2=float32

// SMEM layout (bytes):
//   A tile : [0, 65536)        = 128 rows x 256 k bf16 (32 u16B/row), SW128 atoms
//   B bufs : [65536, 196608)   = 2 buffers x (256 cols x 128 k bf16)
//   rowmax : [196608, 198656)  = 4 x 128 floats
#define SM_A    0u
#define SM_B    65536u
#define SM_MAX  196608u
#define SMEM_BYTES 198656

// ---------------- small helpers ----------------
__device__ __forceinline__ uint32_t smem_u32_addr(const void* p) {
    uint32_t a;
    asm("{ .reg .u64 t; cvta.to.shared.u64 t, %1; cvt.u32.u64 %0, t; }"
        : "=r"(a) : "l"(p));
    return a;
}
__device__ __forceinline__ uint32_t sw128(uint32_t off) {
    return off ^ ((off >> 3) & 0x70u);
}
__device__ __forceinline__ void ldmatrix_x4(uint32_t* r, uint32_t addr) {
    asm volatile("ldmatrix.sync.aligned.m8n8.x4.shared.b16 {%0,%1,%2,%3}, [%4];"
                 : "=r"(r[0]), "=r"(r[1]), "=r"(r[2]), "=r"(r[3]) : "r"(addr));
}
__device__ __forceinline__ void mma16816(float* c, const uint32_t* a,
                                         uint32_t b0, uint32_t b1) {
    asm volatile(
        "mma.sync.aligned.m16n8k16.row.col.f32.bf16.bf16.f32 "
        "{%0,%1,%2,%3}, {%4,%5,%6,%7}, {%8,%9}, {%0,%1,%2,%3};"
        : "+f"(c[0]), "+f"(c[1]), "+f"(c[2]), "+f"(c[3])
        : "r"(a[0]), "r"(a[1]), "r"(a[2]), "r"(a[3]), "r"(b0), "r"(b1));
}
__device__ __forceinline__ void cp_async16(uint32_t saddr, const void* gaddr, int sz) {
    asm volatile("cp.async.ca.shared.global [%0], [%1], 16, %2;"
                 :: "r"(saddr), "l"(gaddr), "r"(sz));
}
__device__ __forceinline__ void cp_commit() {
    asm volatile("cp.async.commit_group;");
}
template <int N>
__device__ __forceinline__ void cp_wait() {
    asm volatile("cp.async.wait_group %0;" :: "n"(N));
}
__device__ __forceinline__ unsigned enc_max(float m) {
    int rep = __float_as_int(m);
    return (rep < 0) ? ~((unsigned)rep) : ((unsigned)rep | 0x80000000u);
}
__device__ __forceinline__ float dec_max(unsigned key) {
    return (key & 0x80000000u) ? __uint_as_float(key & 0x7fffffffu)
                               : __uint_as_float(~key);
}

// ---------------- init ----------------
__global__ void init_kernel() {
    int i = blockIdx.x * blockDim.x + threadIdx.x;
    if (i < B_ * N_) g_rmax[i] = 0u;
    if (i < B_) {
        g_nval[i] = 0; g_ninv[i] = 0; g_nconf[i] = 0; g_contrib[i] = 0.0;
    }
}

// ---------------- mask dtype detection ----------------
__global__ void detect_kernel(const unsigned char* __restrict__ mraw) {
    __shared__ int s_f3f, s_foff;
    if (threadIdx.x == 0) { s_f3f = 0; s_foff = 0; }
    __syncthreads();
    int f3f = 0, foff = 0;
    for (int i = threadIdx.x; i < B_ * N_; i += blockDim.x) {
        unsigned char c = mraw[i];
        if ((i & 3) == 3 && c == 0x3f) f3f = 1;
        if ((i & 3) != 0 && c != 0)    foff = 1;
    }
    if (f3f)  atomicOr(&s_f3f, 1);
    if (foff) atomicOr(&s_foff, 1);
    __syncthreads();
    if (threadIdx.x == 0) g_mask_mode = s_f3f ? 2 : (s_foff ? 1 : 0);
}

// ---------------- normalize + compact (one warp per point) ----------------
// Writes bf16 (for MMA) and fp32 (for exact rescore), both compacted.
__global__ void norm_compact_kernel(const float* __restrict__ feat,
                                    const void*  __restrict__ mraw) {
    int gw   = (int)((blockIdx.x * blockDim.x + threadIdx.x) >> 5);
    int lane = threadIdx.x & 31;
    if (gw >= B_ * N_) return;
    int b = gw / N_;

    int mv = 0;
    if (lane == 0) {
        int mode = g_mask_mode;
        if (mode == 0)      mv = (((const int*)mraw)[gw] != 0);
        else if (mode == 1) mv = (((const unsigned char*)mraw)[gw] != 0);
        else                mv = (((const float*)mraw)[gw] != 0.0f);
    }
    mv = __shfl_sync(0xffffffffu, mv, 0);

    const float* src = feat + (size_t)gw * D_;
    float4 v0 = ((const float4*)src)[lane];
    float4 v1 = ((const float4*)src)[lane + 32];
    float ss = v0.x * v0.x + v0.y * v0.y + v0.z * v0.z + v0.w * v0.w
             + v1.x * v1.x + v1.y * v1.y + v1.z * v1.z + v1.w * v1.w;
#pragma unroll
    for (int o = 16; o; o >>= 1) ss += __shfl_xor_sync(0xffffffffu, ss, o);
    float inv = 1.0f / fmaxf(sqrtf(ss), 1e-12f);
    v0.x *= inv; v0.y *= inv; v0.z *= inv; v0.w *= inv;
    v1.x *= inv; v1.y *= inv; v1.z *= inv; v1.w *= inv;

    int slot = 0;
    if (lane == 0)
        slot = atomicAdd(mv ? &g_nval[b] : &g_ninv[b], 1);
    slot = __shfl_sync(0xffffffffu, slot, 0);

    size_t base = ((size_t)b * N_ + slot) * D_;
    __nv_bfloat16* dh = (mv ? g_Vhi : g_Rhi) + base;
    float*         df = (mv ? g_Vf  : g_Rf)  + base;

    __nv_bfloat162 h0 = __floats2bfloat162_rn(v0.x, v0.y);
    __nv_bfloat162 h1 = __floats2bfloat162_rn(v0.z, v0.w);
    uint2 h; h.x = *(uint32_t*)&h0; h.y = *(uint32_t*)&h1;
    ((uint2*)dh)[lane] = h;
    h0 = __floats2bfloat162_rn(v1.x, v1.y);
    h1 = __floats2bfloat162_rn(v1.z, v1.w);
    h.x = *(uint32_t*)&h0; h.y = *(uint32_t*)&h1;
    ((uint2*)dh)[32 + lane] = h;
    ((float4*)df)[lane]      = v0;
    ((float4*)df)[lane + 32] = v1;
}

// ---------------- pass 1: approx bf16 HMMA sims + row max ----------------
// grid (N_/128, B_, JSPLIT), 256 threads (8 warps: 2 m-warps x 4 n-warps,
// warp tile 64x64). CTA tile 128 rows x 256 cols. A (hi) resident in SMEM,
// B streamed in (256 cols x 128 k) chunks, double buffered. Sims written
// to gmem as fp16; approx row max merged via atomicMax.
__global__ __launch_bounds__(256, 1) void maxsim_p1() {
    extern __shared__ __align__(1024) char smem[];
    int b = blockIdx.y;
    int ni = g_ninv[b], nv = g_nval[b];
    int row0 = blockIdx.x * 128;
    if (row0 >= ni || nv <= 0) return;

    int tiles_total = (nv + 255) >> 8;
    int tiles_per   = (tiles_total + JSPLIT - 1) / JSPLIT;
    int jbeg = blockIdx.z * tiles_per * 256;
    int jend = min(nv, jbeg + tiles_per * 256);
    if (jbeg >= jend) return;

    uint32_t sb = smem_u32_addr(smem);
    int tid = threadIdx.x;
    int lane = tid & 31, warp = tid >> 5;
    int warp_m = warp & 1, warp_n = warp >> 1;   // 2 x 4 warp grid

    const __nv_bfloat16* Rhi_b = g_Rhi + (size_t)b * N_ * D_;
    const __nv_bfloat16* Vhi_b = g_Vhi + (size_t)b * N_ * D_;
    __half* sims_b = g_sims + (size_t)b * N_ * N_;

    // ---- resident A tile: 128 rows x 32 u16B-units (512B/row), SW128 atoms
#pragma unroll
    for (int it = 0; it < 16; ++it) {
        int u = tid + it * 256;            // 0..4095
        int row = u >> 5;
        int ku  = u & 31;
        int gr  = min(row0 + row, ni - 1);
        const uint4* src = (const uint4*)(Rhi_b + (size_t)gr * D_) + ku;
        uint32_t off = SM_A
                     + (uint32_t)((row >> 3) * 4 + (ku >> 3)) * 1024u
                     + (uint32_t)(row & 7) * 128u + (uint32_t)(ku & 7) * 16u;
        *(uint4*)(smem + sw128(off)) = *src;
    }

    float acc[4][8][4];
#pragma unroll
    for (int mf = 0; mf < 4; ++mf)
#pragma unroll
        for (int nf = 0; nf < 8; ++nf)
#pragma unroll
            for (int q = 0; q < 4; ++q) acc[mf][nf][q] = 0.0f;
    float rm[8];
#pragma unroll
    for (int r = 0; r < 8; ++r) rm[r] = -INFINITY;

    int Tj = (jend - jbeg + 255) >> 8;
    int NC = Tj * 2;                       // 2 k128 chunks per j-tile

    // chunk copier: chunk c = (j-tile c>>1, k half c&1). Buffer: 256 cols x 16 u16B.
    auto cp_chunk = [&](int c, int bufsel) {
        int jt = c >> 1, kc = c & 1;
        int col0 = jbeg + jt * 256;
#pragma unroll
        for (int i = 0; i < 16; ++i) {
            int u = tid + i * 256;          // 0..4095
            int col = u >> 4;
            int ku  = u & 15;
            int gc  = col0 + col;
            const void* src = (const void*)(Vhi_b + (size_t)gc * D_ + kc * 128 + ku * 8);
            uint32_t off = SM_B + (uint32_t)bufsel * 65536u
                         + (uint32_t)((col >> 3) * 2 + (ku >> 3)) * 1024u
                         + (uint32_t)(col & 7) * 128u + (uint32_t)(ku & 7) * 16u;
            cp_async16(sb + sw128(off), src, (gc < jend) ? 16 : 0);
        }
        cp_commit();
    };

    cp_chunk(0, 0);
    __syncthreads();   // A tile visible

    for (int i = 0; i < NC; ++i) {
        int bufsel = i & 1;
        int kc = i & 1;
        if (i + 1 < NC) { cp_chunk(i + 1, (i + 1) & 1); cp_wait<1>(); }
        else            { cp_wait<0>(); }
        __syncthreads();

#pragma unroll
        for (int kk = 0; kk < 8; ++kk) {
            uint32_t a[4][4];
#pragma unroll
            for (int mf = 0; mf < 4; ++mf) {
                int row = warp_m * 64 + mf * 16 + (lane & 15);
                int ku  = (kc * 8 + kk) * 2 + (lane >> 4);
                uint32_t off = SM_A
                             + (uint32_t)((row >> 3) * 4 + (ku >> 3)) * 1024u
                             + (uint32_t)(row & 7) * 128u
                             + (uint32_t)(ku & 7) * 16u;
                ldmatrix_x4(a[mf], sb + sw128(off));
            }
            uint32_t bf[4][4];
#pragma unroll
            for (int nf2 = 0; nf2 < 4; ++nf2) {
                int col = warp_n * 64 + nf2 * 16 + (lane & 15);
                int ku  = kk * 2 + (lane >> 4);
                uint32_t off = SM_B + (uint32_t)bufsel * 65536u
                             + (uint32_t)((col >> 3) * 2 + (ku >> 3)) * 1024u
                             + (uint32_t)(col & 7) * 128u
                             + (uint32_t)(ku & 7) * 16u;
                ldmatrix_x4(bf[nf2], sb + sw128(off));
            }
#pragma unroll
            for (int mf = 0; mf < 4; ++mf)
#pragma unroll
                for (int nf2 = 0; nf2 < 4; ++nf2) {
                    mma16816(acc[mf][nf2 * 2],     a[mf], bf[nf2][0], bf[nf2][2]);
                    mma16816(acc[mf][nf2 * 2 + 1], a[mf], bf[nf2][1], bf[nf2][3]);
                }
        }

        if (kc == 1) {
            // end of j-tile: store fp16 sims, fold row max, reset accs
            int jt = i >> 1;
            int colb = jbeg + jt * 256 + warp_n * 64 + 2 * (lane & 3);
#pragma unroll
            for (int mf = 0; mf < 4; ++mf) {
                int r0 = row0 + warp_m * 64 + mf * 16 + (lane >> 2);
                float m0 = rm[mf * 2], m1 = rm[mf * 2 + 1];
#pragma unroll
                for (int nf = 0; nf < 8; ++nf) {
                    float* c = acc[mf][nf];
                    int cc = colb + nf * 8;
                    __half2 h01 = __floats2half2_rn(c[0], c[1]);
                    __half2 h23 = __floats2half2_rn(c[2], c[3]);
                    *(__half2*)(sims_b + (size_t)r0 * N_ + cc)       = h01;
                    *(__half2*)(sims_b + (size_t)(r0 + 8) * N_ + cc) = h23;
                    m0 = fmaxf(m0, fmaxf(c[0], c[1]));
                    m1 = fmaxf(m1, fmaxf(c[2], c[3]));
                    c[0] = c[1] = c[2] = c[3] = 0.0f;
                }
                rm[mf * 2] = m0; rm[mf * 2 + 1] = m1;
            }
        }
        __syncthreads();
    }

    // ---- reduce row maxima across lane quads, then across warp_n
#pragma unroll
    for (int j = 0; j < 8; ++j) {
        rm[j] = fmaxf(rm[j], __shfl_xor_sync(0xffffffffu, rm[j], 1));
        rm[j] = fmaxf(rm[j], __shfl_xor_sync(0xffffffffu, rm[j], 2));
    }
    float* smax = (float*)(smem + SM_MAX);
    if ((lane & 3) == 0) {
#pragma unroll
        for (int mf = 0; mf < 4; ++mf) {
            int rloc = warp_m * 64 + mf * 16 + (lane >> 2);
            smax[warp_n * 128 + rloc]     = rm[mf * 2];
            smax[warp_n * 128 + rloc + 8] = rm[mf * 2 + 1];
        }
    }
    __syncthreads();
    if (tid < 128) {
        int row = row0 + tid;
        if (row < ni) {
            float m = fmaxf(fmaxf(smax[tid], smax[128 + tid]),
                            fmaxf(smax[256 + tid], smax[384 + tid]));
            atomicMax(&g_rmax[b * N_ + row], enc_max(m));
        }
    }
}

// ---------------- rescore: exact fp32 max for near-threshold rows ----------
// One warp per invalid row. Scan approx sims, recompute exact fp32 dots only
// for candidate cols within 2*MARGIN of the approx max.
__global__ void rescore_kernel() {
    int gw   = (int)((blockIdx.x * blockDim.x + threadIdx.x) >> 5);
    int lane = threadIdx.x & 31;
    if (gw >= B_ * N_) return;
    int b = gw / N_, row = gw - b * N_;
    int ni = g_ninv[b], nv = g_nval[b];
    if (row >= ni || nv <= 0) return;

    float m = dec_max(g_rmax[b * N_ + row]);
    if (!(m > CONF_THRESH - MARGIN)) return;   // exact max certainly <= 0.8
    float gate = m - 2.0f * MARGIN;

    const float* rf = g_Rf + ((size_t)b * N_ + row) * D_;
    float rfr[8];
#pragma unroll
    for (int t = 0; t < 8; ++t) rfr[t] = rf[lane + 32 * t];

    const __half* srow = g_sims + (size_t)b * N_ * N_ + (size_t)row * N_;
    const float*  vb   = g_Vf + (size_t)b * N_ * D_;

    float best = -INFINITY;
    int iters = (nv + 31) >> 5;
    for (int it = 0; it < iters; ++it) {
        int j = it * 32 + lane;
        float s = (j < nv) ? __half2float(srow[j]) : -2.0f;
        unsigned mset = __ballot_sync(0xffffffffu, s >= gate);
        while (mset) {
            int src = __ffs(mset) - 1;
            mset &= mset - 1;
            int col = __shfl_sync(0xffffffffu, j, src);
            const float* vc = vb + (size_t)col * D_;
            float sum = 0.0f;
#pragma unroll
            for (int t = 0; t < 8; ++t) sum = fmaf(rfr[t], vc[lane + 32 * t], sum);
#pragma unroll
            for (int o = 16; o; o >>= 1) sum += __shfl_xor_sync(0xffffffffu, sum, o);
            best = fmaxf(best, sum);
        }
    }
    if (lane == 0 && best > CONF_THRESH) {
        atomicAdd(&g_contrib[b], (double)(1.0f - best));
        atomicAdd(&g_nconf[b], 1);
    }
}

// ---------------- finalize ----------------
__global__ void finalize_kernel(float* out) {
    if (threadIdx.x == 0 && blockIdx.x == 0) {
        double tl = 0.0, tp = 0.0;
        for (int b = 0; b < B_; ++b) {
            int ni = g_ninv[b], nvv = g_nval[b], nc = g_nconf[b];
            bool active = (nc > 0) && (nvv > 0) && (ni > 0);
            if (active) {
                double pseudo = g_contrib[b] / (double)(nc > 1 ? nc : 1);
                tl += pseudo * (double)ni;
                tp += (double)ni;
            }
        }
        out[0] = (tp > 0.0) ? (float)(0.01 * tl / tp) : 0.0f;
    }
}

// ---------------- launch ----------------
extern "C" void kernel_launch(void* const* d_in, const int* in_sizes, int n_in,
                              void* d_out, int out_size) {
    int fi = 0, mi = 1;
    if (n_in >= 2 && in_sizes[0] < in_sizes[1]) { fi = 1; mi = 0; }
    const float* feat = (const float*)d_in[fi];
    const void*  mask = d_in[mi];

    cudaFuncSetAttribute(maxsim_p1, cudaFuncAttributeMaxDynamicSharedMemorySize,
                         SMEM_BYTES);

    init_kernel<<<(B_ * N_ + 255) / 256, 256>>>();
    detect_kernel<<<1, 1024>>>((const unsigned char*)mask);
    norm_compact_kernel<<<(B_ * N_ * 32 + 255) / 256, 256>>>(feat, mask);
    dim3 g(N_ / 128, B_, JSPLIT);
    maxsim_p1<<<g, 256, SMEM_BYTES>>>();
    rescore_kernel<<<(B_ * N_ * 32 + 255) / 256, 256>>>();
    finalize_kernel<<<1, 32>>>((float*)d_out);
}